// round 1
// baseline (speedup 1.0000x reference)
#include <cuda_runtime.h>

// SheafLoss: B=4 T=1024 P=16 D=64 R=32 K=64, TAU=1
// inputs: d_in[0]=m (B,T,P,D) f32, d_in[1]=w (B,T,P) f32,
//         d_in[2]=p (B,T,P,K) f32, d_in[3]=patch_centers (R,D) f32
// output: scalar f32 loss

#define BT    4096
#define P_    16
#define D_    64
#define R_    32
#define K_    64
#define NPAIR 496   // R*(R-1)/2

__device__ double g_acc;
__device__ float  g_omega[R_ * R_];

// ---------------------------------------------------------------------------
// Kernel A: omega[r][s] = exp(-||c_r - c_s||^2) (TAU=1), zero accumulator.
// 1 block, 1024 threads (one per (r,s)).
// ---------------------------------------------------------------------------
__global__ void sheaf_setup_kernel(const float* __restrict__ gc) {
    int tid = threadIdx.x;
    int r = tid >> 5, s = tid & 31;
    float cd = 0.f;
#pragma unroll 8
    for (int d = 0; d < D_; d++) {
        float df = gc[r * D_ + d] - gc[s * D_ + d];
        cd = fmaf(df, df, cd);
    }
    g_omega[tid] = expf(-cd);
    if (tid == 0) g_acc = 0.0;
}

// ---------------------------------------------------------------------------
// Kernel B: one CTA per (b,t). 256 threads = 8 warps.
// ---------------------------------------------------------------------------
__global__ void __launch_bounds__(256, 5) sheaf_main_kernel(
    const float* __restrict__ gm,
    const float* __restrict__ gw,
    const float* __restrict__ gp)
{
    __shared__ float s_c[R_][D_ + 1];   // centers, padded (conflict-free lane=r reads)
    __shared__ float s_m[P_ * D_];      // m tile
    __shared__ float s_p[P_ * K_];      // p tile
    __shared__ float s_sm[P_][R_];      // start_mass
    __shared__ float s_tm[R_];          // 1/(total_mass_r + 1e-6)
    __shared__ float s_pb[R_][K_];      // p_bar
    __shared__ float s_pl[R_][K_];      // p_bar * log(p_bar + 1e-8)
    __shared__ float s_E[R_];           // entropy-like term per r
    __shared__ float s_w[P_];
    __shared__ float s_om[R_ * R_];
    __shared__ unsigned char s_qr[NPAIR], s_qs[NPAIR];
    __shared__ float s_warp[8];
    // centers cached per-CTA from global (L2-resident, 8KB)
    extern __shared__ float dummy_unused[]; // (none)

    const int tid  = threadIdx.x;
    const int lane = tid & 31;
    const int wid  = tid >> 5;
    const int bt   = blockIdx.x;

    const float* mrow = gm + (size_t)bt * (P_ * D_);
    const float* prow = gp + (size_t)bt * (P_ * K_);

    // ---- loads ----
    {
        const float* gc = (const float*)0; // set below via g_omega trick? no: pass centers via shared path
    }
    // centers come via global pointer stored in constant-like global? Simpler:
    // we re-read centers from gm? NO — centers are d_in[3]; passed separately.
    // (handled: this kernel takes centers as 4th arg — see signature fix below)
    // --- placeholder removed in final signature ---

    // (real body continues in sheaf_main_kernel2)
    (void)mrow; (void)prow; (void)lane; (void)wid; (void)s_c; (void)s_warp;
    (void)s_qr; (void)s_qs; (void)s_om; (void)s_w; (void)s_E; (void)s_pl;
    (void)s_pb; (void)s_tm; (void)s_sm; (void)s_p; (void)s_m;
}

// Full implementation (with centers argument).
__global__ void __launch_bounds__(256, 5) sheaf_kernel(
    const float* __restrict__ gm,
    const float* __restrict__ gw,
    const float* __restrict__ gp,
    const float* __restrict__ gc)
{
    __shared__ float s_c[R_][D_ + 1];
    __shared__ float s_m[P_ * D_];
    __shared__ float s_p[P_ * K_];
    __shared__ float s_sm[P_][R_];
    __shared__ float s_tm[R_];
    __shared__ float s_pb[R_][K_];
    __shared__ float s_pl[R_][K_];
    __shared__ float s_E[R_];
    __shared__ float s_w[P_];
    __shared__ float s_om[R_ * R_];
    __shared__ unsigned char s_qr[NPAIR], s_qs[NPAIR];
    __shared__ float s_warp[8];

    const int tid  = threadIdx.x;
    const int lane = tid & 31;
    const int wid  = tid >> 5;
    const int bt   = blockIdx.x;

    const float* mrow = gm + (size_t)bt * (P_ * D_);
    const float* prow = gp + (size_t)bt * (P_ * K_);

    // ---- cooperative loads ----
    for (int i = tid; i < R_ * D_; i += 256) s_c[i / D_][i % D_] = gc[i];
    for (int i = tid; i < P_ * D_; i += 256) s_m[i] = mrow[i];
    for (int i = tid; i < P_ * K_; i += 256) s_p[i] = prow[i];
    for (int i = tid; i < R_ * R_; i += 256) s_om[i] = g_omega[i];
    if (tid < P_) s_w[tid] = gw[(size_t)bt * P_ + tid];
    // pair index table (r<s)
    for (int q = tid; q < NPAIR; q += 256) {
        int rr = 0, rem = q;
        while (rem >= 31 - rr) { rem -= 31 - rr; rr++; }
        s_qr[q] = (unsigned char)rr;
        s_qs[q] = (unsigned char)(rr + 1 + rem);
    }
    __syncthreads();

    // ---- step 1: dists + softmax + start_mass, fused in registers ----
    // warp `wid` handles patch rows p0=wid, p1=wid+8; lane = center index r.
    {
        const int p0 = wid, p1 = wid + 8;
        const int r = lane;
        float a0 = 0.f, a1 = 0.f;
#pragma unroll 8
        for (int d = 0; d < D_; d++) {
            float cv = s_c[r][d];                 // conflict-free (stride 65)
            float m0 = s_m[p0 * D_ + d];          // broadcast
            float m1 = s_m[p1 * D_ + d];          // broadcast
            float d0 = m0 - cv;
            float d1 = m1 - cv;
            a0 = fmaf(d0, d0, a0);
            a1 = fmaf(d1, d1, a1);
        }
        // softmax over r (lane dim), logits = -dist (TAU=1): use min-dist
        float mn0 = a0, mn1 = a1;
#pragma unroll
        for (int off = 16; off; off >>= 1) {
            mn0 = fminf(mn0, __shfl_xor_sync(0xffffffffu, mn0, off));
            mn1 = fminf(mn1, __shfl_xor_sync(0xffffffffu, mn1, off));
        }
        float e0 = __expf(mn0 - a0);
        float e1 = __expf(mn1 - a1);
        float sm0 = e0, sm1 = e1;
#pragma unroll
        for (int off = 16; off; off >>= 1) {
            sm0 += __shfl_xor_sync(0xffffffffu, sm0, off);
            sm1 += __shfl_xor_sync(0xffffffffu, sm1, off);
        }
        float f0 = s_w[p0] / sm0;
        float f1 = s_w[p1] / sm1;
        s_sm[p0][lane] = e0 * f0;
        s_sm[p1][lane] = e1 * f1;
    }
    __syncthreads();

    // ---- step 2: total mass per r (warp 0) ----
    if (wid == 0) {
        float a = 0.f;
#pragma unroll
        for (int pp = 0; pp < P_; pp++) a += s_sm[pp][lane];
        s_tm[lane] = 1.0f / (a + 1e-6f);
    }
    __syncthreads();

    // ---- step 3: p_bar[r][k] + pointwise p*log(p+eps) ----
#pragma unroll
    for (int j = 0; j < 8; j++) {
        int o = tid + 256 * j;
        int r = o >> 6, k = o & 63;
        float acc = 0.f;
#pragma unroll
        for (int pp = 0; pp < P_; pp++)
            acc = fmaf(s_p[pp * K_ + k], s_sm[pp][r], acc);
        float pb = acc * s_tm[r];
        s_pb[r][k] = pb;
        s_pl[r][k] = pb * __logf(pb + 1e-8f);
    }
    __syncthreads();

    // ---- step 4: E_r = sum_k p_bar*log(p_bar+eps) ----
    for (int rr = wid; rr < R_; rr += 8) {
        float t = s_pl[rr][lane] + s_pl[rr][lane + 32];
#pragma unroll
        for (int off = 16; off; off >>= 1)
            t += __shfl_xor_sync(0xffffffffu, t, off);
        if (lane == 0) s_E[rr] = t;
    }
    __syncthreads();

    // ---- step 5: pair loop. js = 0.5*(E_r+E_s) - sum_k m*log(m+eps) ----
    float wacc = 0.f;
    for (int q = wid; q < NPAIR; q += 8) {
        int r = s_qr[q], s = s_qs[q];
        float pr0 = s_pb[r][lane],      ps0 = s_pb[s][lane];
        float pr1 = s_pb[r][lane + 32], ps1 = s_pb[s][lane + 32];
        float m0 = 0.5f * (pr0 + ps0);
        float m1 = 0.5f * (pr1 + ps1);
        float c = fmaf(m0, __logf(m0 + 1e-8f), m1 * __logf(m1 + 1e-8f));
#pragma unroll
        for (int off = 16; off; off >>= 1)
            c += __shfl_xor_sync(0xffffffffu, c, off);
        if (lane == 0) {
            float js = 0.5f * (s_E[r] + s_E[s]) - c;
            wacc = fmaf(s_om[r * R_ + s], js, wacc);
        }
    }
    if (lane == 0) s_warp[wid] = wacc;
    __syncthreads();
    if (tid == 0) {
        float a = 0.f;
#pragma unroll
        for (int i = 0; i < 8; i++) a += s_warp[i];
        atomicAdd(&g_acc, (double)a);
    }
}

// ---------------------------------------------------------------------------
// Kernel C: finalize
// ---------------------------------------------------------------------------
__global__ void sheaf_finalize_kernel(float* __restrict__ out) {
    out[0] = (float)(g_acc / (496.0 + 1e-8));
}

extern "C" void kernel_launch(void* const* d_in, const int* in_sizes, int n_in,
                              void* d_out, int out_size) {
    const float* m = (const float*)d_in[0];
    const float* w = (const float*)d_in[1];
    const float* p = (const float*)d_in[2];
    const float* c = (const float*)d_in[3];
    float* out = (float*)d_out;
    (void)in_sizes; (void)n_in; (void)out_size;

    sheaf_setup_kernel<<<1, 1024>>>(c);
    sheaf_kernel<<<BT, 256>>>(m, w, p, c);
    sheaf_finalize_kernel<<<1, 1>>>(out);
}

// round 3
// speedup vs baseline: 2.0611x; 2.0611x over previous
#include <cuda_runtime.h>

// SheafLoss: B=4 T=1024 P=16 D=64 R=32 K=64, TAU=1
// d_in[0]=m (B,T,P,D) f32, d_in[1]=w (B,T,P) f32,
// d_in[2]=p (B,T,P,K) f32, d_in[3]=patch_centers (R,D) f32
// out: scalar f32

#define BT    4096
#define P_    16
#define D_    64
#define R_    32
#define K_    64

__device__ double g_acc;
__device__ float  g_omega[R_ * R_];
__device__ float  g_cn[R_];

// ---------------------------------------------------------------------------
// Setup: omega[r][s] = exp(-||c_r-c_s||^2), cn[r] = |c_r|^2, zero accumulator.
// __launch_bounds__(1024) is required: 1024 threads demand <=64 regs/thread.
// ---------------------------------------------------------------------------
__global__ void __launch_bounds__(1024) sheaf_setup_kernel(const float* __restrict__ gc) {
    __shared__ float sc[R_][D_ + 1];
    int tid = threadIdx.x;
    for (int i = tid; i < R_ * D_; i += 1024) sc[i >> 6][i & 63] = gc[i];
    __syncthreads();
    int r = tid >> 5, s = tid & 31;
    float cd = 0.f;
#pragma unroll 8
    for (int d = 0; d < D_; d++) {
        float df = sc[r][d] - sc[s][d];
        cd = fmaf(df, df, cd);
    }
    g_omega[tid] = expf(-cd);
    if (s == 0) {
        float cn = 0.f;
#pragma unroll 8
        for (int d = 0; d < D_; d++) cn = fmaf(sc[r][d], sc[r][d], cn);
        g_cn[r] = cn;
    }
    if (tid == 0) g_acc = 0.0;
}

// ---------------------------------------------------------------------------
// Main: one CTA per (b,t), 256 threads = 8 warps.
// ---------------------------------------------------------------------------
__global__ void __launch_bounds__(256, 5) sheaf_kernel(
    const float* __restrict__ gm,
    const float* __restrict__ gw,
    const float* __restrict__ gp,
    const float* __restrict__ gc)
{
    __shared__ float  s_cT[D_][R_ + 1];  // centers transposed [d][r], padded
    __shared__ float  s_m[P_ * D_];
    __shared__ float  s_p[P_ * K_];
    __shared__ float  s_sm[P_][R_];      // start_mass
    __shared__ float  s_tm[R_];          // 1/(total_mass_r + 1e-6)
    __shared__ float2 s_pb[R_][R_];      // p_bar packed: [r][lane]=(k, k+32)
    __shared__ float  s_E[R_];           // sum_k p_bar*log(p_bar+eps)
    __shared__ float  s_w[P_];
    __shared__ float  s_om[R_ * R_];
    __shared__ float  s_cn[R_];
    __shared__ float  s_red[8];

    const int tid  = threadIdx.x;
    const int lane = tid & 31;
    const int wid  = tid >> 5;
    const int bt   = blockIdx.x;

    const float* mrow = gm + (size_t)bt * (P_ * D_);
    const float* prow = gp + (size_t)bt * (P_ * K_);

    // ---- cooperative loads ----
    for (int i = tid; i < R_ * D_; i += 256) s_cT[i & 63][i >> 6] = gc[i];
    for (int i = tid; i < P_ * D_; i += 256) s_m[i] = mrow[i];
    for (int i = tid; i < P_ * K_; i += 256) s_p[i] = prow[i];
    for (int i = tid; i < R_ * R_; i += 256) s_om[i] = g_omega[i];
    if (tid < R_) s_cn[tid] = g_cn[tid];
    if (tid < P_) s_w[tid]  = gw[(size_t)bt * P_ + tid];
    __syncthreads();

    // ---- step 1: logits = 2*m.c - |c|^2 (|m|^2 cancels in softmax) ----
    // warp wid: patches p0=wid, p1=wid+8; lane = r.
    {
        const int p0 = wid, p1 = wid + 8;
        const int r = lane;
        float a0 = 0.f, a1 = 0.f;
#pragma unroll
        for (int d = 0; d < D_; d += 4) {
            float4 mv0 = *(const float4*)&s_m[p0 * D_ + d];
            float4 mv1 = *(const float4*)&s_m[p1 * D_ + d];
            float c0 = s_cT[d + 0][r];
            float c1 = s_cT[d + 1][r];
            float c2 = s_cT[d + 2][r];
            float c3 = s_cT[d + 3][r];
            a0 = fmaf(mv0.x, c0, fmaf(mv0.y, c1, fmaf(mv0.z, c2, fmaf(mv0.w, c3, a0))));
            a1 = fmaf(mv1.x, c0, fmaf(mv1.y, c1, fmaf(mv1.z, c2, fmaf(mv1.w, c3, a1))));
        }
        float cn = s_cn[r];
        float l0 = fmaf(2.f, a0, -cn);
        float l1 = fmaf(2.f, a1, -cn);
        float mx0 = l0, mx1 = l1;
#pragma unroll
        for (int off = 16; off; off >>= 1) {
            mx0 = fmaxf(mx0, __shfl_xor_sync(0xffffffffu, mx0, off));
            mx1 = fmaxf(mx1, __shfl_xor_sync(0xffffffffu, mx1, off));
        }
        float e0 = __expf(l0 - mx0);
        float e1 = __expf(l1 - mx1);
        float sm0 = e0, sm1 = e1;
#pragma unroll
        for (int off = 16; off; off >>= 1) {
            sm0 += __shfl_xor_sync(0xffffffffu, sm0, off);
            sm1 += __shfl_xor_sync(0xffffffffu, sm1, off);
        }
        s_sm[p0][lane] = e0 * (s_w[p0] / sm0);
        s_sm[p1][lane] = e1 * (s_w[p1] / sm1);
    }
    __syncthreads();

    // ---- step 2: 1/(total_mass_r + eps) ----
    if (wid == 0) {
        float a = 0.f;
#pragma unroll
        for (int pp = 0; pp < P_; pp++) a += s_sm[pp][lane];
        s_tm[lane] = 1.0f / (a + 1e-6f);
    }
    __syncthreads();

    // ---- step 3: p_bar (float2-packed) + E_r; p-slice hoisted over 4 rows ----
    {
        float acc[4][2] = {{0.f,0.f},{0.f,0.f},{0.f,0.f},{0.f,0.f}};
#pragma unroll
        for (int pp = 0; pp < P_; pp++) {
            float sp0 = s_p[pp * K_ + lane];
            float sp1 = s_p[pp * K_ + lane + 32];
#pragma unroll
            for (int j = 0; j < 4; j++) {
                float g = s_sm[pp][wid + 8 * j];
                acc[j][0] = fmaf(sp0, g, acc[j][0]);
                acc[j][1] = fmaf(sp1, g, acc[j][1]);
            }
        }
#pragma unroll
        for (int j = 0; j < 4; j++) {
            int r = wid + 8 * j;
            float t = s_tm[r];
            float pb0 = acc[j][0] * t;
            float pb1 = acc[j][1] * t;
            s_pb[r][lane] = make_float2(pb0, pb1);
            float e = fmaf(pb0, __logf(pb0 + 1e-8f), pb1 * __logf(pb1 + 1e-8f));
#pragma unroll
            for (int off = 16; off; off >>= 1)
                e += __shfl_xor_sync(0xffffffffu, e, off);
            if (lane == 0) s_E[r] = e;
        }
    }
    __syncthreads();

    // ---- pair loop: rows {w, 15-w, 16+w, 31-w} => exactly 62 pairs/warp.
    // js = 0.5*(E_r+E_s) - sum_k m*log(m+eps); per-lane acc, butterfly once.
    {
        float lacc = 0.f, eacc = 0.f;
        int rows[4] = { wid, 15 - wid, 16 + wid, 31 - wid };
#pragma unroll
        for (int i = 0; i < 4; i++) {
            int r = rows[i];
            float2 pr = s_pb[r][lane];
            float  Er = s_E[r];
            for (int s = r + 1; s < R_; s++) {
                float2 ps = s_pb[s][lane];
                float  om = s_om[r * R_ + s];
                float m0 = 0.5f * (pr.x + ps.x);
                float m1 = 0.5f * (pr.y + ps.y);
                float t = fmaf(m0, __logf(m0 + 1e-8f), m1 * __logf(m1 + 1e-8f));
                lacc = fmaf(om, t, lacc);
                eacc = fmaf(om, Er + s_E[s], eacc);
            }
        }
#pragma unroll
        for (int off = 16; off; off >>= 1)
            lacc += __shfl_xor_sync(0xffffffffu, lacc, off);
        if (lane == 0) s_red[wid] = fmaf(0.5f, eacc, -lacc);
    }
    __syncthreads();
    if (tid == 0) {
        float a = 0.f;
#pragma unroll
        for (int i = 0; i < 8; i++) a += s_red[i];
        atomicAdd(&g_acc, (double)a);
    }
}

__global__ void sheaf_finalize_kernel(float* __restrict__ out) {
    out[0] = (float)(g_acc / (496.0 + 1e-8));
}

extern "C" void kernel_launch(void* const* d_in, const int* in_sizes, int n_in,
                              void* d_out, int out_size) {
    const float* m = (const float*)d_in[0];
    const float* w = (const float*)d_in[1];
    const float* p = (const float*)d_in[2];
    const float* c = (const float*)d_in[3];
    float* out = (float*)d_out;
    (void)in_sizes; (void)n_in; (void)out_size;

    sheaf_setup_kernel<<<1, 1024>>>(c);
    sheaf_kernel<<<BT, 256>>>(m, w, p, c);
    sheaf_finalize_kernel<<<1, 1>>>(out);
}

// round 4
// speedup vs baseline: 2.3410x; 1.1358x over previous
#include <cuda_runtime.h>

// SheafLoss: B=4 T=1024 P=16 D=64 R=32 K=64, TAU=1
// d_in[0]=m (B,T,P,D) f32, d_in[1]=w (B,T,P) f32,
// d_in[2]=p (B,T,P,K) f32, d_in[3]=patch_centers (R,D) f32
// out: scalar f32

#define BT    4096
#define P_    16
#define D_    64
#define R_    32
#define K_    64

__device__ double g_acc;
__device__ float  g_omega[R_ * R_];
__device__ float  g_cn[R_];

// ---------------------------------------------------------------------------
// Setup: 4 blocks x 256 threads; block b handles rows [8b, 8b+8).
// omega[r][s] = exp(-||c_r-c_s||^2), cn[r] = |c_r|^2, zero accumulator.
// ---------------------------------------------------------------------------
__global__ void __launch_bounds__(256) sheaf_setup_kernel(const float* __restrict__ gc) {
    __shared__ float sc[R_][D_ + 1];
    const int tid = threadIdx.x;
    for (int i = tid; i < R_ * D_; i += 256) sc[i >> 6][i & 63] = gc[i];
    __syncthreads();
    const int r = blockIdx.x * 8 + (tid >> 5);
    const int s = tid & 31;
    float cd = 0.f;
#pragma unroll 8
    for (int d = 0; d < D_; d++) {
        float df = sc[r][d] - sc[s][d];
        cd = fmaf(df, df, cd);
    }
    g_omega[r * R_ + s] = expf(-cd);
    // cn[r]: lane-parallel square-sum + butterfly
    float t = sc[r][s] * sc[r][s] + sc[r][s + 32] * sc[r][s + 32];
#pragma unroll
    for (int off = 16; off; off >>= 1)
        t += __shfl_xor_sync(0xffffffffu, t, off);
    if (s == 0) g_cn[r] = t;
    if (r == 0 && s == 0) g_acc = 0.0;
}

// ---------------------------------------------------------------------------
// Main: one CTA per (b,t), 256 threads = 8 warps.
// ---------------------------------------------------------------------------
__global__ void __launch_bounds__(256, 5) sheaf_kernel(
    const float* __restrict__ gm,
    const float* __restrict__ gw,
    const float* __restrict__ gp,
    const float* __restrict__ gc)
{
    __shared__ float  s_cT[D_][R_ + 1];  // centers transposed [d][r], padded
    __shared__ float  s_m[P_ * D_];
    __shared__ float  s_p[P_ * K_];
    __shared__ float  s_sm[P_][R_];      // start_mass
    __shared__ float  s_tm[R_];          // 1/(total_mass_r + 1e-6)
    __shared__ float2 s_pb[R_][R_];      // p_bar packed: [r][lane]=(k, k+32)
    __shared__ float  s_E[R_];           // sum_k p_bar*log(p_bar+eps)
    __shared__ float  s_w[P_];
    __shared__ float  s_cn[R_];
    __shared__ float  s_red[8];

    const int tid  = threadIdx.x;
    const int lane = tid & 31;
    const int wid  = tid >> 5;
    const int bt   = blockIdx.x;

    const float* mrow = gm + (size_t)bt * (P_ * D_);
    const float* prow = gp + (size_t)bt * (P_ * K_);

    // ---- loads (m, p vectorized; c transposed scalar) ----
    ((float4*)s_m)[tid] = ((const float4*)mrow)[tid];   // 1024 floats exactly
    ((float4*)s_p)[tid] = ((const float4*)prow)[tid];   // 1024 floats exactly
    for (int i = tid; i < R_ * D_; i += 256) s_cT[i & 63][i >> 6] = gc[i];
    if (tid < R_) s_cn[tid] = g_cn[tid];
    if (tid < P_) s_w[tid]  = gw[(size_t)bt * P_ + tid];
    __syncthreads();

    // ---- step 1: logits = 2*m.c - |c|^2; warps 0..3, 4 patches each ----
    if (wid < 4) {
        const int r = lane;
        float a[4] = {0.f, 0.f, 0.f, 0.f};
#pragma unroll
        for (int d = 0; d < D_; d += 4) {
            float c0 = s_cT[d + 0][r];
            float c1 = s_cT[d + 1][r];
            float c2 = s_cT[d + 2][r];
            float c3 = s_cT[d + 3][r];
#pragma unroll
            for (int j = 0; j < 4; j++) {
                float4 mv = *(const float4*)&s_m[(wid + 4 * j) * D_ + d];
                a[j] = fmaf(mv.x, c0, fmaf(mv.y, c1, fmaf(mv.z, c2, fmaf(mv.w, c3, a[j]))));
            }
        }
        const float cn = s_cn[r];
        float l[4], mx[4], e[4], sm[4];
#pragma unroll
        for (int j = 0; j < 4; j++) { l[j] = fmaf(2.f, a[j], -cn); mx[j] = l[j]; }
#pragma unroll
        for (int off = 16; off; off >>= 1)
#pragma unroll
            for (int j = 0; j < 4; j++)
                mx[j] = fmaxf(mx[j], __shfl_xor_sync(0xffffffffu, mx[j], off));
#pragma unroll
        for (int j = 0; j < 4; j++) { e[j] = __expf(l[j] - mx[j]); sm[j] = e[j]; }
#pragma unroll
        for (int off = 16; off; off >>= 1)
#pragma unroll
            for (int j = 0; j < 4; j++)
                sm[j] += __shfl_xor_sync(0xffffffffu, sm[j], off);
#pragma unroll
        for (int j = 0; j < 4; j++) {
            int p = wid + 4 * j;
            s_sm[p][lane] = e[j] * (s_w[p] / sm[j]);
        }
    }
    __syncthreads();

    // ---- step 2: 1/(total_mass_r + eps) ----
    if (wid == 0) {
        float a = 0.f;
#pragma unroll
        for (int pp = 0; pp < P_; pp++) a += s_sm[pp][lane];
        s_tm[lane] = 1.0f / (a + 1e-6f);
    }
    __syncthreads();

    // ---- step 3: p_bar (float2-packed) + E_r; p-slice hoisted over 4 rows ----
    {
        float acc[4][2] = {{0.f,0.f},{0.f,0.f},{0.f,0.f},{0.f,0.f}};
#pragma unroll
        for (int pp = 0; pp < P_; pp++) {
            float sp0 = s_p[pp * K_ + lane];
            float sp1 = s_p[pp * K_ + lane + 32];
#pragma unroll
            for (int j = 0; j < 4; j++) {
                float g = s_sm[pp][wid + 8 * j];
                acc[j][0] = fmaf(sp0, g, acc[j][0]);
                acc[j][1] = fmaf(sp1, g, acc[j][1]);
            }
        }
#pragma unroll
        for (int j = 0; j < 4; j++) {
            int r = wid + 8 * j;
            float t = s_tm[r];
            float pb0 = acc[j][0] * t;
            float pb1 = acc[j][1] * t;
            s_pb[r][lane] = make_float2(pb0, pb1);
            float e = fmaf(pb0, __logf(pb0 + 1e-8f), pb1 * __logf(pb1 + 1e-8f));
#pragma unroll
            for (int off = 16; off; off >>= 1)
                e += __shfl_xor_sync(0xffffffffu, e, off);
            if (lane == 0) s_E[r] = e;
        }
    }
    __syncthreads();

    // ---- pair loop: rows {w, 15-w, 16+w, 31-w} => exactly 62 pairs/warp ----
    // js = 0.5*(E_r+E_s) - sum_k m*log(m+eps), weighted by omega.
    // E-part hoisted to per-row rank-1 reductions (lane = s):
    //   eterm += E_r*sum_{s>r} om[r][s] + sum_{s>r} om[r][s]*E[s]
    // Inner loop touches only s_pb (LDS.64) + om via __ldg (LSU pipe).
    {
        const float Ev = s_E[lane];       // row-independent, hoisted
        float eterm = 0.f, lacc = 0.f;
        const int rows[4] = { wid, 15 - wid, 16 + wid, 31 - wid };
#pragma unroll
        for (int i = 0; i < 4; i++) {
            const int r = rows[i];
            // per-row omega-weighted E reduction
            float omv = __ldg(&g_omega[r * R_ + lane]);
            float t1 = (lane > r) ? omv : 0.f;
            float t2 = (lane > r) ? omv * Ev : 0.f;
#pragma unroll
            for (int off = 16; off; off >>= 1) {
                t1 += __shfl_xor_sync(0xffffffffu, t1, off);
                t2 += __shfl_xor_sync(0xffffffffu, t2, off);
            }
            eterm += fmaf(s_E[r], t1, t2);   // lane-uniform
            // per-lane m*log(m) part
            float2 pr = s_pb[r][lane];
            for (int s = r + 1; s < R_; s++) {
                float2 ps = s_pb[s][lane];
                float om = __ldg(&g_omega[r * R_ + s]);
                float m0 = 0.5f * (pr.x + ps.x);
                float m1 = 0.5f * (pr.y + ps.y);
                float t = fmaf(m0, __logf(m0 + 1e-8f), m1 * __logf(m1 + 1e-8f));
                lacc = fmaf(om, t, lacc);
            }
        }
#pragma unroll
        for (int off = 16; off; off >>= 1)
            lacc += __shfl_xor_sync(0xffffffffu, lacc, off);
        if (lane == 0) s_red[wid] = fmaf(0.5f, eterm, -lacc);
    }
    __syncthreads();
    if (tid == 0) {
        float a = 0.f;
#pragma unroll
        for (int i = 0; i < 8; i++) a += s_red[i];
        atomicAdd(&g_acc, (double)a);
    }
}

__global__ void sheaf_finalize_kernel(float* __restrict__ out) {
    out[0] = (float)(g_acc / (496.0 + 1e-8));
}

extern "C" void kernel_launch(void* const* d_in, const int* in_sizes, int n_in,
                              void* d_out, int out_size) {
    const float* m = (const float*)d_in[0];
    const float* w = (const float*)d_in[1];
    const float* p = (const float*)d_in[2];
    const float* c = (const float*)d_in[3];
    float* out = (float*)d_out;
    (void)in_sizes; (void)n_in; (void)out_size;

    sheaf_setup_kernel<<<4, 256>>>(c);
    sheaf_kernel<<<BT, 256>>>(m, w, p, c);
    sheaf_finalize_kernel<<<1, 1>>>(out);
}